// round 7
// baseline (speedup 1.0000x reference)
#include <cuda_runtime.h>

// QuantumConvLayer: probs = [c^4, c^2 s^2, s^4, s^2 c^2],
// c^2 = (1+cos x)/2, s^2 = (1-cos x)/2, x = inputs[i,0].
// HBM-bound streaming: 256MB read + 256MB write (both mandatory, 512MB total).
// R6: paired-row ownership — each thread processes rows (2i, 2i+1), so its
// input loads and output stores are contiguous 32B; a warp's access pair spans
// one contiguous 1KB block. 4 rows/thread via two adjacent pairs, front-batched.

#define TPB 256
#define PAIRS 2                          // pairs of rows per thread
#define ROWS_PER_BLOCK (TPB * 2 * PAIRS) // 1024

__device__ __forceinline__ float4 qprobs(float x)
{
    float cx = __cosf(x);
    float c2 = 0.5f + 0.5f * cx;   // cos^2(x/2)
    float s2 = 0.5f - 0.5f * cx;   // sin^2(x/2)
    float cs = c2 * s2;
    return make_float4(c2 * c2, cs, s2 * s2, cs);
}

__global__ void __launch_bounds__(TPB) qconv_kernel(
    const float4* __restrict__ in,  // [N] rows of 16B; only .x used
    float4* __restrict__ out,       // [N]
    int n)
{
    int tile = blockIdx.x * ROWS_PER_BLOCK;
    int t = threadIdx.x;

    // Pair p: rows base, base+1 with base = tile + p*(2*TPB) + 2*t
    float x[2 * PAIRS];
    int base[PAIRS];

    // Front-batch all loads: per thread 2*PAIRS independent LDG.128s,
    // each pair contiguous 32B; warp covers a contiguous 1KB span per pair.
#pragma unroll
    for (int p = 0; p < PAIRS; p++) {
        base[p] = tile + p * (2 * TPB) + 2 * t;
        if (base[p] + 1 < n) {
            x[2 * p]     = __ldg(in + base[p]).x;
            x[2 * p + 1] = __ldg(in + base[p] + 1).x;
        } else {
            x[2 * p]     = (base[p] < n) ? __ldg(in + base[p]).x : 0.0f;
            x[2 * p + 1] = 0.0f;
        }
    }

#pragma unroll
    for (int p = 0; p < PAIRS; p++) {
        if (base[p] + 1 < n) {
            out[base[p]]     = qprobs(x[2 * p]);
            out[base[p] + 1] = qprobs(x[2 * p + 1]);
        } else if (base[p] < n) {
            out[base[p]]     = qprobs(x[2 * p]);
        }
    }
}

extern "C" void kernel_launch(void* const* d_in, const int* in_sizes, int n_in,
                              void* d_out, int out_size)
{
    const float4* in = (const float4*)d_in[0];
    float4* out = (float4*)d_out;
    int n = in_sizes[0] / 4;   // rows

    int grid = (n + ROWS_PER_BLOCK - 1) / ROWS_PER_BLOCK;
    qconv_kernel<<<grid, TPB>>>(in, out, n);
}

// round 8
// speedup vs baseline: 1.0191x; 1.0191x over previous
#include <cuda_runtime.h>

// QuantumConvLayer: probs = [c^4, c^2 s^2, s^4, s^2 c^2],
// c^2 = (1+cos x)/2, s^2 = (1-cos x)/2, x = inputs[i,0].
// HBM-bound streaming: 256MB read + 256MB write (both mandatory).
// FINAL (= R5, best measured): flat grid, TPB=256, RPT=4 front-batched dense
// LDG.128 row loads (warp = contiguous 512B) + dense STG.128 stores.
// Measured: 74.56us kernel, 6.45TB/s (80.7% of HBM spec) — mixed-stream floor.
// R6 (paired-row, 32B/lane stride) regressed via doubled L1tex wavefronts;
// R4 (persistent single wave) regressed via lost cross-tile overlap.

#define RPT 4
#define TPB 256
#define ROWS_PER_BLOCK (RPT * TPB)   // 1024

__device__ __forceinline__ float4 qprobs(float x)
{
    float cx = __cosf(x);
    float c2 = 0.5f + 0.5f * cx;   // cos^2(x/2)
    float s2 = 0.5f - 0.5f * cx;   // sin^2(x/2)
    float cs = c2 * s2;
    return make_float4(c2 * c2, cs, s2 * s2, cs);
}

__global__ void __launch_bounds__(TPB) qconv_kernel(
    const float4* __restrict__ in,  // [N] rows, 16B each; only .x (col 0) used
    float4* __restrict__ out,       // [N]
    int n)
{
    int tile = blockIdx.x * ROWS_PER_BLOCK;
    int t = threadIdx.x;

    float x[RPT];
    int row[RPT];

    // Front-batch 4 independent dense LDG.128s (warp = 512B contiguous each)
#pragma unroll
    for (int k = 0; k < RPT; k++) {
        row[k] = tile + t + TPB * k;
        x[k] = (row[k] < n) ? __ldg(in + row[k]).x : 0.0f;
    }

#pragma unroll
    for (int k = 0; k < RPT; k++) {
        if (row[k] < n)
            out[row[k]] = qprobs(x[k]);
    }
}

extern "C" void kernel_launch(void* const* d_in, const int* in_sizes, int n_in,
                              void* d_out, int out_size)
{
    const float4* in = (const float4*)d_in[0];
    float4* out = (float4*)d_out;
    int n = in_sizes[0] / 4;   // rows

    int grid = (n + ROWS_PER_BLOCK - 1) / ROWS_PER_BLOCK;
    qconv_kernel<<<grid, TPB>>>(in, out, n);
}